// round 1
// baseline (speedup 1.0000x reference)
#include <cuda_runtime.h>

#define ALPHA   0.2f
#define NEG_BIG -1000000000000.0f

static constexpr int BB = 4;
static constexpr int NN = 4096;
static constexpr int CC = 64;
static constexpr int TI = 128;   // i-rows per CTA in k_pv
static constexpr int TJ = 64;    // j-chunk in k_pv

// Scratch (allocation-free rule: __device__ globals)
__device__ float g_h [BB * NN * CC];
__device__ float g_f1[BB * NN];
__device__ float g_f2[BB * NN];
__device__ float g_m [BB * NN];
__device__ float g_s [BB * NN];

// ---------------------------------------------------------------------------
// Kernel 1: h = x @ W ; f1 = h . a[:64] ; f2 = h . a[64:]
// 256 threads = 4 rows x 64 features. W cached in shared.
// ---------------------------------------------------------------------------
__global__ __launch_bounds__(256) void k_proj(const float* __restrict__ x,
                                              const float* __restrict__ W,
                                              const float* __restrict__ a)
{
    __shared__ float Ws[64][64];
    __shared__ float xs[4][64];
    __shared__ float red1[8], red2[8];

    int tid  = threadIdx.x;
    int row0 = blockIdx.x * 4;

    for (int idx = tid; idx < 64 * 64; idx += 256)
        Ws[idx >> 6][idx & 63] = W[idx];
    {
        int r = tid >> 6, k = tid & 63;
        xs[r][k] = x[(size_t)(row0 + r) * CC + k];
    }
    __syncthreads();

    int r = tid >> 6;
    int f = tid & 63;
    float hv = 0.f;
#pragma unroll
    for (int k = 0; k < 64; k++)
        hv = fmaf(xs[r][k], Ws[k][f], hv);

    int g = row0 + r;                 // global row index (b*NN + n)
    g_h[(size_t)g * CC + f] = hv;

    float v1 = hv * a[f];
    float v2 = hv * a[64 + f];
#pragma unroll
    for (int off = 16; off; off >>= 1) {
        v1 += __shfl_down_sync(0xffffffffu, v1, off);
        v2 += __shfl_down_sync(0xffffffffu, v2, off);
    }
    int w = tid >> 5;
    if ((tid & 31) == 0) { red1[w] = v1; red2[w] = v2; }
    __syncthreads();
    if (tid < 4) {
        g_f1[row0 + tid] = red1[2 * tid] + red1[2 * tid + 1];
        g_f2[row0 + tid] = red2[2 * tid] + red2[2 * tid + 1];
    }
}

// ---------------------------------------------------------------------------
// Kernel 2: per (b,i): m = max_j e_ij, s = sum_j exp(e_ij - m)
// One block per i (adj row read once, shared across the 4 batches).
// Two passes per thread (max, then sum) -> exactly one exp per element.
// ---------------------------------------------------------------------------
__global__ __launch_bounds__(256) void k_maxsum(const int* __restrict__ adj)
{
    int i   = blockIdx.x;
    int tid = threadIdx.x;
    const int* __restrict__ arow = adj + (size_t)i * NN;

    float f1v[BB], mloc[BB], sloc[BB];
#pragma unroll
    for (int b = 0; b < BB; b++) {
        f1v[b]  = g_f1[b * NN + i];
        mloc[b] = -3.0e38f;
        sloc[b] = 0.f;
    }

    // pass 1: thread-local max
    for (int j = tid; j < NN; j += 256) {
        int av = arow[j];
#pragma unroll
        for (int b = 0; b < BB; b++) {
            float z = f1v[b] + g_f2[b * NN + j];
            float e = (av > 0) ? ((z > 0.f) ? z : ALPHA * z) : NEG_BIG;
            mloc[b] = fmaxf(mloc[b], e);
        }
    }
    // pass 2: thread-local sum of exp(e - mloc)
    for (int j = tid; j < NN; j += 256) {
        int av = arow[j];
#pragma unroll
        for (int b = 0; b < BB; b++) {
            float z = f1v[b] + g_f2[b * NN + j];
            float e = (av > 0) ? ((z > 0.f) ? z : ALPHA * z) : NEG_BIG;
            sloc[b] += __expf(e - mloc[b]);
        }
    }

    __shared__ float sm[BB][256];
    __shared__ float ss[BB][256];
#pragma unroll
    for (int b = 0; b < BB; b++) { sm[b][tid] = mloc[b]; ss[b][tid] = sloc[b]; }
    __syncthreads();
    for (int st = 128; st; st >>= 1) {
        if (tid < st) {
#pragma unroll
            for (int b = 0; b < BB; b++) {
                float m1 = sm[b][tid], m2 = sm[b][tid + st];
                float mm = fmaxf(m1, m2);
                ss[b][tid] = ss[b][tid] * __expf(m1 - mm)
                           + ss[b][tid + st] * __expf(m2 - mm);
                sm[b][tid] = mm;
            }
        }
        __syncthreads();
    }
    if (tid == 0) {
#pragma unroll
        for (int b = 0; b < BB; b++) {
            g_m[b * NN + i] = sm[b][0];
            g_s[b * NN + i] = ss[b][0];
        }
    }
}

// ---------------------------------------------------------------------------
// Kernel 3: out[b,i,:] = relu( (1/s_i) * sum_j exp(e_ij - m_i) * h[b,j,:] )
// Grid (NN/TI, BB). 256 threads. Register tile: 8 rows x 4 cols per thread.
// Shared: H chunk [64][64], P tile [128][65] (padded: half-warp row groups
// differ by 8 rows -> bank offset 8*65 % 32 = 8, conflict-free).
// ---------------------------------------------------------------------------
static constexpr int HS_OFF = 0;                   // 64*64   = 4096 floats
static constexpr int PS_OFF = HS_OFF + TJ * CC;    // 128*65  = 8320 floats
static constexpr int F1_OFF = PS_OFF + TI * 65;    // 128
static constexpr int MS_OFF = F1_OFF + TI;         // 128
static constexpr int IS_OFF = MS_OFF + TI;         // 128
static constexpr int F2_OFF = IS_OFF + TI;         // 64
static constexpr int SMEM_FLOATS = F2_OFF + TJ;    // 12864 floats = 51456 B

__global__ __launch_bounds__(256) void k_pv(const int* __restrict__ adj,
                                            float* __restrict__ out)
{
    extern __shared__ float smem[];
    float* hs   = smem + HS_OFF;
    float* ps   = smem + PS_OFF;
    float* f1s  = smem + F1_OFF;
    float* ms   = smem + MS_OFF;
    float* invs = smem + IS_OFF;
    float* f2s  = smem + F2_OFF;

    int b   = blockIdx.y;
    int i0  = blockIdx.x * TI;
    int tid = threadIdx.x;

    if (tid < TI) {
        int gi = b * NN + i0 + tid;
        f1s[tid]  = g_f1[gi];
        ms[tid]   = g_m[gi];
        invs[tid] = 1.0f / g_s[gi];
    }

    float acc[8][4];
#pragma unroll
    for (int k = 0; k < 8; k++)
#pragma unroll
        for (int c = 0; c < 4; c++) acc[k][c] = 0.f;

    int fg   = tid & 15;          // feature group: f = fg*4 .. fg*4+3
    int rb   = (tid >> 4) * 8;    // 8 i-rows per thread
    int w    = tid >> 5;          // warp 0..7
    int lane = tid & 31;

    for (int jc = 0; jc < NN; jc += TJ) {
        __syncthreads();          // protect hs/ps from previous iteration

        // load H chunk [TJ x 64] (contiguous, float4-coalesced)
        {
            const float4* src = (const float4*)(g_h + ((size_t)b * NN + jc) * CC);
            float4* dst = (float4*)hs;
            for (int idx = tid; idx < TJ * CC / 4; idx += 256)
                dst[idx] = src[idx];
        }
        if (tid < TJ) f2s[tid] = g_f2[b * NN + jc + tid];
        __syncthreads();

        // compute P tile: each warp owns 16 i-rows, lanes sweep j (coalesced adj)
#pragma unroll 4
        for (int it = 0; it < 16; it++) {
            int ti = w * 16 + it;
            float base = f1s[ti];
            float mi   = ms[ti];
            const int* __restrict__ ar = adj + (size_t)(i0 + ti) * NN + jc;
            int   a0 = ar[lane];
            int   a1 = ar[lane + 32];
            float z0 = base + f2s[lane];
            float z1 = base + f2s[lane + 32];
            float e0 = (a0 > 0) ? ((z0 > 0.f) ? z0 : ALPHA * z0) : NEG_BIG;
            float e1 = (a1 > 0) ? ((z1 > 0.f) ? z1 : ALPHA * z1) : NEG_BIG;
            ps[ti * 65 + lane]      = __expf(e0 - mi);
            ps[ti * 65 + lane + 32] = __expf(e1 - mi);
        }
        __syncthreads();

        // accumulate: acc[k][:] += P[rb+k][tj] * H[tj][fg*4 .. +3]
        const float4* hs4 = (const float4*)hs;
#pragma unroll 4
        for (int tj = 0; tj < TJ; tj++) {
            float4 hv = hs4[tj * 16 + fg];
#pragma unroll
            for (int k = 0; k < 8; k++) {
                float p = ps[(rb + k) * 65 + tj];
                acc[k][0] = fmaf(p, hv.x, acc[k][0]);
                acc[k][1] = fmaf(p, hv.y, acc[k][1]);
                acc[k][2] = fmaf(p, hv.z, acc[k][2]);
                acc[k][3] = fmaf(p, hv.w, acc[k][3]);
            }
        }
    }

    // epilogue: scale by 1/s, relu, vectorized store
#pragma unroll
    for (int k = 0; k < 8; k++) {
        float is = invs[rb + k];
        float4 o;
        o.x = fmaxf(acc[k][0] * is, 0.f);
        o.y = fmaxf(acc[k][1] * is, 0.f);
        o.z = fmaxf(acc[k][2] * is, 0.f);
        o.w = fmaxf(acc[k][3] * is, 0.f);
        size_t idx = (((size_t)b * NN + i0 + rb + k) * CC + fg * 4) >> 2;
        ((float4*)out)[idx] = o;
    }
}

// ---------------------------------------------------------------------------
extern "C" void kernel_launch(void* const* d_in, const int* in_sizes, int n_in,
                              void* d_out, int out_size)
{
    const float* x   = (const float*)d_in[0];   // [4,4096,64] f32
    const int*   adj = (const int*)  d_in[1];   // [4096,4096] i32
    const float* W   = (const float*)d_in[2];   // [64,64] f32
    const float* a   = (const float*)d_in[3];   // [128,1] f32
    float*       out = (float*)d_out;           // [4,4096,64] f32

    k_proj<<<BB * NN / 4, 256>>>(x, W, a);
    k_maxsum<<<NN, 256>>>(adj);

    cudaFuncSetAttribute(k_pv, cudaFuncAttributeMaxDynamicSharedMemorySize,
                         SMEM_FLOATS * (int)sizeof(float));
    dim3 grid(NN / TI, BB);
    k_pv<<<grid, 256, SMEM_FLOATS * sizeof(float)>>>(adj, out);
}

// round 3
// speedup vs baseline: 1.7281x; 1.7281x over previous
#include <cuda_runtime.h>
#include <cuda_bf16.h>
#include <cstdint>
#include <cstddef>

#define ALPHA 0.2f

static constexpr int BB = 4;
static constexpr int NN = 4096;
static constexpr int CC = 64;

// ---------------------------------------------------------------------------
// Scratch (__device__ globals: allocation-free rule)
// ---------------------------------------------------------------------------
__device__ __nv_bfloat16 g_hThi[BB * CC * NN];   // [b][f][n]  hi bf16 of h^T
__device__ __nv_bfloat16 g_hTlo[BB * CC * NN];   // [b][f][n]  lo bf16 of h^T
__device__ float g_f1 [BB * NN];                 // f1[b][n]
__device__ float g_f2t[NN * BB];                 // f2 transposed: [n][b]
__device__ float g_m  [BB * NN];                 // row max of e (post-leaky)

__device__ __forceinline__ uint32_t pack_bf2(float lo, float hi) {
    __nv_bfloat16 a = __float2bfloat16_rn(lo);
    __nv_bfloat16 b = __float2bfloat16_rn(hi);
    return (uint32_t)__bfloat16_as_ushort(a)
         | ((uint32_t)__bfloat16_as_ushort(b) << 16);
}

__device__ __forceinline__ void mma_bf16(float c[4], uint32_t a0, uint32_t a1,
                                         uint32_t a2, uint32_t a3,
                                         uint32_t b0, uint32_t b1) {
    asm volatile(
        "mma.sync.aligned.m16n8k16.row.col.f32.bf16.bf16.f32 "
        "{%0,%1,%2,%3}, {%4,%5,%6,%7}, {%8,%9}, {%0,%1,%2,%3};"
        : "+f"(c[0]), "+f"(c[1]), "+f"(c[2]), "+f"(c[3])
        : "r"(a0), "r"(a1), "r"(a2), "r"(a3), "r"(b0), "r"(b1));
}

// ---------------------------------------------------------------------------
// Kernel 1: h = x@W ; f1 = h.a1 ; f2 = h.a2 ; h^T stored as bf16 hi/lo planes.
// 16 rows per CTA, 256 threads.
// ---------------------------------------------------------------------------
__global__ __launch_bounds__(256) void k_proj(const float* __restrict__ x,
                                              const float* __restrict__ W,
                                              const float* __restrict__ a)
{
    __shared__ float Ws[64][64];
    __shared__ float xs[16][64];
    __shared__ float hsm[64][17];          // [f][r] for transposed write
    __shared__ float red1[8][4], red2[8][4];

    int tid  = threadIdx.x;
    int row0 = blockIdx.x * 16;            // flattened b*NN + n, multiple of 16
    int bb   = row0 >> 12;
    int n0   = row0 & (NN - 1);

#pragma unroll
    for (int t = 0; t < 16; t++) {
        int idx = tid + t * 256;
        Ws[idx >> 6][idx & 63] = W[idx];
    }
#pragma unroll
    for (int t = 0; t < 4; t++) {
        int idx = tid + t * 256;
        xs[idx >> 6][idx & 63] = x[(size_t)row0 * CC + idx];
    }
    __syncthreads();

    int slot = tid >> 6, f = tid & 63, w = tid >> 5;
    float a1v = a[f], a2v = a[64 + f];

#pragma unroll
    for (int rr = 0; rr < 4; ++rr) {
        int r = slot * 4 + rr;
        float hv = 0.f;
#pragma unroll
        for (int k = 0; k < 64; k++) hv = fmaf(xs[r][k], Ws[k][f], hv);
        hsm[f][r] = hv;

        float v1 = hv * a1v, v2 = hv * a2v;
#pragma unroll
        for (int off = 16; off; off >>= 1) {
            v1 += __shfl_down_sync(0xffffffffu, v1, off);
            v2 += __shfl_down_sync(0xffffffffu, v2, off);
        }
        if ((tid & 31) == 0) { red1[w][rr] = v1; red2[w][rr] = v2; }
    }
    __syncthreads();

    // transposed bf16 hi/lo write: idx -> (f, pair p), pairs along n
#pragma unroll
    for (int t = 0; t < 2; t++) {
        int idx = tid + t * 256;           // 0..511
        int ff = idx >> 3, p = idx & 7;
        float v0 = hsm[ff][2 * p], v1 = hsm[ff][2 * p + 1];
        __nv_bfloat16 h0 = __float2bfloat16_rn(v0);
        __nv_bfloat16 h1 = __float2bfloat16_rn(v1);
        float l0 = v0 - __bfloat162float(h0);
        float l1 = v1 - __bfloat162float(h1);
        size_t base = ((size_t)(bb * CC + ff)) * NN + n0 + 2 * p;
        *(uint32_t*)(g_hThi + base) =
            (uint32_t)__bfloat16_as_ushort(h0) |
            ((uint32_t)__bfloat16_as_ushort(h1) << 16);
        *(uint32_t*)(g_hTlo + base) = pack_bf2(l0, l1);
    }

    if (tid < 16) {
        int s = tid & 3, rr = tid >> 2;
        int g = row0 + s * 4 + rr;
        g_f1[g] = red1[2 * s][rr] + red1[2 * s + 1][rr];
        float v2 = red2[2 * s][rr] + red2[2 * s + 1][rr];
        g_f2t[(g & (NN - 1)) * 4 + (g >> 12)] = v2;
    }
}

// ---------------------------------------------------------------------------
// Kernel 2: g_m[b][i] = leaky(f1[b][i] + max_{j: adj_ij>0} f2[b][j])
// (leaky_relu monotone -> no exp in max pass). adj row cached in SMEM.
// ---------------------------------------------------------------------------
__global__ __launch_bounds__(256) void k_rowmax(const int* __restrict__ adj)
{
    __shared__ int   arow[NN];
    __shared__ float wred[8][BB];

    int i = blockIdx.x, tid = threadIdx.x;
    const int4* src = (const int4*)(adj + ((size_t)i << 12));
    int4* dst = (int4*)arow;
#pragma unroll
    for (int t = 0; t < 4; t++) dst[tid + t * 256] = src[tid + t * 256];
    __syncthreads();

    float M2[BB];
#pragma unroll
    for (int b = 0; b < BB; b++) M2[b] = -3.0e38f;

#pragma unroll 4
    for (int t = 0; t < 16; t++) {
        int j  = tid + t * 256;
        int av = arow[j];
        float4 f2 = *(const float4*)(g_f2t + j * 4);
        M2[0] = fmaxf(M2[0], (av > 0) ? f2.x : -3.0e38f);
        M2[1] = fmaxf(M2[1], (av > 0) ? f2.y : -3.0e38f);
        M2[2] = fmaxf(M2[2], (av > 0) ? f2.z : -3.0e38f);
        M2[3] = fmaxf(M2[3], (av > 0) ? f2.w : -3.0e38f);
    }
#pragma unroll
    for (int off = 16; off; off >>= 1)
#pragma unroll
        for (int b = 0; b < BB; b++)
            M2[b] = fmaxf(M2[b], __shfl_xor_sync(0xffffffffu, M2[b], off));
    if ((tid & 31) == 0)
#pragma unroll
        for (int b = 0; b < BB; b++) wred[tid >> 5][b] = M2[b];
    __syncthreads();
    if (tid < BB) {
        float m2 = wred[0][tid];
#pragma unroll
        for (int w = 1; w < 8; w++) m2 = fmaxf(m2, wred[w][tid]);
        float z = g_f1[tid * NN + i] + m2;
        g_m[tid * NN + i] = fmaxf(z, ALPHA * z);
    }
}

// ---------------------------------------------------------------------------
// Kernel 3: PV via legacy bf16 mma.sync (3-product split: ~fp32 accuracy).
// CTA = 128 i-rows x 64 feats of one batch, 8 warps (16 rows each).
// P fragments computed directly in mma register layout (no A SMEM).
// Row sums for softmax denominator accumulated per-lane, quad-reduced.
// ---------------------------------------------------------------------------
static constexpr int BPITCH = 144;                   // 72 bf16 row pitch (pad)
static constexpr int BPLANE = 64 * BPITCH;           // 9216 B per plane

__global__ __launch_bounds__(256) void k_pv(const int* __restrict__ adj,
                                            float* __restrict__ out)
{
    __shared__ __align__(16) char bsm[2 * BPLANE];   // [hi | lo] H^T tiles
    __shared__ float f2s[64];

    const int tid = threadIdx.x, wid = tid >> 5, lane = tid & 31;
    const int g = lane >> 2, tg = lane & 3;
    const int b = blockIdx.y, i0 = blockIdx.x * 128;

    const int gi0 = i0 + wid * 16 + g;
    const int gi1 = gi0 + 8;
    const float f1_0 = g_f1[b * NN + gi0], m0 = g_m[b * NN + gi0];
    const float f1_1 = g_f1[b * NN + gi1], m1 = g_m[b * NN + gi1];
    const int* __restrict__ ar0 = adj + ((size_t)gi0 << 12);
    const int* __restrict__ ar1 = adj + ((size_t)gi1 << 12);

    float C[8][4];
#pragma unroll
    for (int n = 0; n < 8; n++)
#pragma unroll
        for (int k = 0; k < 4; k++) C[n][k] = 0.f;
    float rs0 = 0.f, rs1 = 0.f;

    for (int c = 0; c < 64; ++c) {
        const int jc = c * 64;
        __syncthreads();
        // ---- stage H^T hi/lo tiles [64 f][64 j] + f2 slice ----
#pragma unroll
        for (int t = 0; t < 2; t++) {
            int idx = tid + t * 256;              // 0..511
            int ff = idx >> 3, q = idx & 7;
            size_t src = (size_t)(b * CC + ff) * NN + jc;
            *(float4*)(bsm + ff * BPITCH + q * 16) =
                ((const float4*)(g_hThi + src))[q];
            *(float4*)(bsm + BPLANE + ff * BPITCH + q * 16) =
                ((const float4*)(g_hTlo + src))[q];
        }
        if (tid < 64) f2s[tid] = g_f2t[(jc + tid) * 4 + b];
        __syncthreads();

#pragma unroll
        for (int ks = 0; ks < 4; ++ks) {
            const int c0 = 2 * tg + 16 * ks;
            float f2a = f2s[c0],     f2b = f2s[c0 + 1];
            float f2c = f2s[c0 + 8], f2d = f2s[c0 + 9];
            int2 A00 = *(const int2*)(ar0 + jc + c0);
            int2 A01 = *(const int2*)(ar0 + jc + c0 + 8);
            int2 A10 = *(const int2*)(ar1 + jc + c0);
            int2 A11 = *(const int2*)(ar1 + jc + c0 + 8);

            // P values for this lane's 8 fragment slots
            float z, l;
            z = f1_0 + f2a; l = fmaxf(z, ALPHA * z) - m0;
            float p00 = (A00.x > 0) ? __expf(l) : 0.f;
            z = f1_0 + f2b; l = fmaxf(z, ALPHA * z) - m0;
            float p01 = (A00.y > 0) ? __expf(l) : 0.f;
            z = f1_0 + f2c; l = fmaxf(z, ALPHA * z) - m0;
            float p02 = (A01.x > 0) ? __expf(l) : 0.f;
            z = f1_0 + f2d; l = fmaxf(z, ALPHA * z) - m0;
            float p03 = (A01.y > 0) ? __expf(l) : 0.f;
            z = f1_1 + f2a; l = fmaxf(z, ALPHA * z) - m1;
            float p10 = (A10.x > 0) ? __expf(l) : 0.f;
            z = f1_1 + f2b; l = fmaxf(z, ALPHA * z) - m1;
            float p11 = (A10.y > 0) ? __expf(l) : 0.f;
            z = f1_1 + f2c; l = fmaxf(z, ALPHA * z) - m1;
            float p12 = (A11.x > 0) ? __expf(l) : 0.f;
            z = f1_1 + f2d; l = fmaxf(z, ALPHA * z) - m1;
            float p13 = (A11.y > 0) ? __expf(l) : 0.f;

            rs0 += (p00 + p01) + (p02 + p03);
            rs1 += (p10 + p11) + (p12 + p13);

            // bf16 split -> A fragments (hi and lo)
            __nv_bfloat16 h00 = __float2bfloat16_rn(p00);
            __nv_bfloat16 h01 = __float2bfloat16_rn(p01);
            __nv_bfloat16 h02 = __float2bfloat16_rn(p02);
            __nv_bfloat16 h03 = __float2bfloat16_rn(p03);
            __nv_bfloat16 h10 = __float2bfloat16_rn(p10);
            __nv_bfloat16 h11 = __float2bfloat16_rn(p11);
            __nv_bfloat16 h12 = __float2bfloat16_rn(p12);
            __nv_bfloat16 h13 = __float2bfloat16_rn(p13);
            uint32_t ahi0 = (uint32_t)__bfloat16_as_ushort(h00) |
                            ((uint32_t)__bfloat16_as_ushort(h01) << 16);
            uint32_t ahi1 = (uint32_t)__bfloat16_as_ushort(h10) |
                            ((uint32_t)__bfloat16_as_ushort(h11) << 16);
            uint32_t ahi2 = (uint32_t)__bfloat16_as_ushort(h02) |
                            ((uint32_t)__bfloat16_as_ushort(h03) << 16);
            uint32_t ahi3 = (uint32_t)__bfloat16_as_ushort(h12) |
                            ((uint32_t)__bfloat16_as_ushort(h13) << 16);
            uint32_t alo0 = pack_bf2(p00 - __bfloat162float(h00),
                                     p01 - __bfloat162float(h01));
            uint32_t alo1 = pack_bf2(p10 - __bfloat162float(h10),
                                     p11 - __bfloat162float(h11));
            uint32_t alo2 = pack_bf2(p02 - __bfloat162float(h02),
                                     p03 - __bfloat162float(h03));
            uint32_t alo3 = pack_bf2(p12 - __bfloat162float(h12),
                                     p13 - __bfloat162float(h13));

            // B fragments from SMEM (row n, u32 at j = 2tg+16ks (+8))
#pragma unroll
            for (int n0 = 0; n0 < 8; ++n0) {
                const uint32_t* rhi =
                    (const uint32_t*)(bsm + (n0 * 8 + g) * BPITCH);
                const uint32_t* rlo =
                    (const uint32_t*)(bsm + BPLANE + (n0 * 8 + g) * BPITCH);
                uint32_t bhi0 = rhi[tg + 8 * ks];
                uint32_t bhi1 = rhi[tg + 8 * ks + 4];
                uint32_t blo0 = rlo[tg + 8 * ks];
                uint32_t blo1 = rlo[tg + 8 * ks + 4];
                mma_bf16(C[n0], ahi0, ahi1, ahi2, ahi3, bhi0, bhi1);
                mma_bf16(C[n0], ahi0, ahi1, ahi2, ahi3, blo0, blo1);
                mma_bf16(C[n0], alo0, alo1, alo2, alo3, bhi0, bhi1);
            }
        }
    }

    // ---- softmax denominators: quad reduce (lanes 4g..4g+3 share rows) ----
    rs0 += __shfl_xor_sync(0xffffffffu, rs0, 1);
    rs0 += __shfl_xor_sync(0xffffffffu, rs0, 2);
    rs1 += __shfl_xor_sync(0xffffffffu, rs1, 1);
    rs1 += __shfl_xor_sync(0xffffffffu, rs1, 2);
    float iv0 = 1.0f / rs0, iv1 = 1.0f / rs1;

    // ---- epilogue: scale, relu, store float2 per slot ----
    float* o0 = out + ((size_t)b * NN + gi0) * CC + 2 * tg;
    float* o1 = out + ((size_t)b * NN + gi1) * CC + 2 * tg;
#pragma unroll
    for (int n0 = 0; n0 < 8; ++n0) {
        float2 v0, v1;
        v0.x = fmaxf(C[n0][0] * iv0, 0.f);
        v0.y = fmaxf(C[n0][1] * iv0, 0.f);
        v1.x = fmaxf(C[n0][2] * iv1, 0.f);
        v1.y = fmaxf(C[n0][3] * iv1, 0.f);
        *(float2*)(o0 + n0 * 8) = v0;
        *(float2*)(o1 + n0 * 8) = v1;
    }
}

// ---------------------------------------------------------------------------
extern "C" void kernel_launch(void* const* d_in, const int* in_sizes, int n_in,
                              void* d_out, int out_size)
{
    const float* x   = (const float*)d_in[0];   // [4,4096,64] f32
    const int*   adj = (const int*)  d_in[1];   // [4096,4096] i32
    const float* W   = (const float*)d_in[2];   // [64,64] f32
    const float* a   = (const float*)d_in[3];   // [128,1] f32
    float*       out = (float*)d_out;           // [4,4096,64] f32

    k_proj<<<BB * NN / 16, 256>>>(x, W, a);
    k_rowmax<<<NN, 256>>>(adj);
    dim3 grid(NN / 128, BB);
    k_pv<<<grid, 256>>>(adj, out);
}

// round 4
// speedup vs baseline: 2.1193x; 1.2264x over previous
#include <cuda_runtime.h>
#include <cuda_bf16.h>
#include <cstdint>
#include <cstddef>

#define ALPHA 0.2f
#define L2E   1.4426950408889634f

static constexpr int BB = 4;
static constexpr int NN = 4096;
static constexpr int CC = 64;

// ---------------------------------------------------------------------------
// Scratch (__device__ globals: allocation-free rule)
// ---------------------------------------------------------------------------
__device__ __nv_bfloat16 g_hThi[BB * CC * NN];   // [b][f][n]  hi bf16 of h^T
__device__ __nv_bfloat16 g_hTlo[BB * CC * NN];   // [b][f][n]  lo bf16 of h^T
__device__ float    g_f1 [BB * NN];              // f1[b][n]
__device__ float    g_f2t[NN * BB];              // f2 transposed: [n][b]
__device__ float    g_m  [BB * NN];              // row max of e (post-leaky)
__device__ uint32_t g_adjbits[NN * 128];         // adj rows bit-packed

__device__ __forceinline__ uint32_t smem_u32(const void* p) {
    uint32_t a;
    asm("{ .reg .u64 t; cvta.to.shared.u64 t, %1; cvt.u32.u64 %0, t; }"
        : "=r"(a) : "l"(p));
    return a;
}

__device__ __forceinline__ uint32_t pack_bf2(float lo, float hi) {
    __nv_bfloat16 a = __float2bfloat16_rn(lo);
    __nv_bfloat16 b = __float2bfloat16_rn(hi);
    return (uint32_t)__bfloat16_as_ushort(a)
         | ((uint32_t)__bfloat16_as_ushort(b) << 16);
}

__device__ __forceinline__ void mma_bf16(float c[4], uint32_t a0, uint32_t a1,
                                         uint32_t a2, uint32_t a3,
                                         uint32_t b0, uint32_t b1) {
    asm volatile(
        "mma.sync.aligned.m16n8k16.row.col.f32.bf16.bf16.f32 "
        "{%0,%1,%2,%3}, {%4,%5,%6,%7}, {%8,%9}, {%0,%1,%2,%3};"
        : "+f"(c[0]), "+f"(c[1]), "+f"(c[2]), "+f"(c[3])
        : "r"(a0), "r"(a1), "r"(a2), "r"(a3), "r"(b0), "r"(b1));
}

// ---------------------------------------------------------------------------
// Kernel 1: h = x@W ; f1 = h.a1 ; f2 = h.a2 ; h^T stored as bf16 hi/lo planes.
// ---------------------------------------------------------------------------
__global__ __launch_bounds__(256) void k_proj(const float* __restrict__ x,
                                              const float* __restrict__ W,
                                              const float* __restrict__ a)
{
    __shared__ float Ws[64][64];
    __shared__ float xs[16][64];
    __shared__ float hsm[64][17];
    __shared__ float red1[8][4], red2[8][4];

    int tid  = threadIdx.x;
    int row0 = blockIdx.x * 16;
    int bb   = row0 >> 12;
    int n0   = row0 & (NN - 1);

#pragma unroll
    for (int t = 0; t < 16; t++) {
        int idx = tid + t * 256;
        Ws[idx >> 6][idx & 63] = W[idx];
    }
#pragma unroll
    for (int t = 0; t < 4; t++) {
        int idx = tid + t * 256;
        xs[idx >> 6][idx & 63] = x[(size_t)row0 * CC + idx];
    }
    __syncthreads();

    int slot = tid >> 6, f = tid & 63, w = tid >> 5;
    float a1v = a[f], a2v = a[64 + f];

#pragma unroll
    for (int rr = 0; rr < 4; ++rr) {
        int r = slot * 4 + rr;
        float hv = 0.f;
#pragma unroll
        for (int k = 0; k < 64; k++) hv = fmaf(xs[r][k], Ws[k][f], hv);
        hsm[f][r] = hv;

        float v1 = hv * a1v, v2 = hv * a2v;
#pragma unroll
        for (int off = 16; off; off >>= 1) {
            v1 += __shfl_down_sync(0xffffffffu, v1, off);
            v2 += __shfl_down_sync(0xffffffffu, v2, off);
        }
        if ((tid & 31) == 0) { red1[w][rr] = v1; red2[w][rr] = v2; }
    }
    __syncthreads();

#pragma unroll
    for (int t = 0; t < 2; t++) {
        int idx = tid + t * 256;           // 0..511
        int ff = idx >> 3, p = idx & 7;
        float v0 = hsm[ff][2 * p], v1 = hsm[ff][2 * p + 1];
        __nv_bfloat16 h0 = __float2bfloat16_rn(v0);
        __nv_bfloat16 h1 = __float2bfloat16_rn(v1);
        float l0 = v0 - __bfloat162float(h0);
        float l1 = v1 - __bfloat162float(h1);
        size_t base = ((size_t)(bb * CC + ff)) * NN + n0 + 2 * p;
        *(uint32_t*)(g_hThi + base) =
            (uint32_t)__bfloat16_as_ushort(h0) |
            ((uint32_t)__bfloat16_as_ushort(h1) << 16);
        *(uint32_t*)(g_hTlo + base) = pack_bf2(l0, l1);
    }

    if (tid < 16) {
        int s = tid & 3, rr = tid >> 2;
        int g = row0 + s * 4 + rr;
        g_f1[g] = red1[2 * s][rr] + red1[2 * s + 1][rr];
        float v2 = red2[2 * s][rr] + red2[2 * s + 1][rr];
        g_f2t[(g & (NN - 1)) * 4 + (g >> 12)] = v2;
    }
}

// ---------------------------------------------------------------------------
// Kernel 2: row max (no exp needed: leaky is monotone) + adj bit-packing.
// ---------------------------------------------------------------------------
__global__ __launch_bounds__(256) void k_rowmax(const int* __restrict__ adj)
{
    __shared__ int   arow[NN];
    __shared__ float wred[8][BB];

    int i = blockIdx.x, tid = threadIdx.x;
    int wid = tid >> 5, lane = tid & 31;
    const int4* src = (const int4*)(adj + ((size_t)i << 12));
    int4* dst = (int4*)arow;
#pragma unroll
    for (int t = 0; t < 4; t++) dst[tid + t * 256] = src[tid + t * 256];
    __syncthreads();

    // pack adjacency bits: warp wid covers j in [wid*512, wid*512+512)
#pragma unroll
    for (int t = 0; t < 16; t++) {
        int j = wid * 512 + t * 32 + lane;
        unsigned bal = __ballot_sync(0xffffffffu, arow[j] > 0);
        if (lane == 0) g_adjbits[(size_t)i * 128 + wid * 16 + t] = bal;
    }

    float M2[BB];
#pragma unroll
    for (int b = 0; b < BB; b++) M2[b] = -3.0e38f;

#pragma unroll 4
    for (int t = 0; t < 16; t++) {
        int j  = tid + t * 256;
        int av = arow[j];
        float4 f2 = *(const float4*)(g_f2t + j * 4);
        M2[0] = fmaxf(M2[0], (av > 0) ? f2.x : -3.0e38f);
        M2[1] = fmaxf(M2[1], (av > 0) ? f2.y : -3.0e38f);
        M2[2] = fmaxf(M2[2], (av > 0) ? f2.z : -3.0e38f);
        M2[3] = fmaxf(M2[3], (av > 0) ? f2.w : -3.0e38f);
    }
#pragma unroll
    for (int off = 16; off; off >>= 1)
#pragma unroll
        for (int b = 0; b < BB; b++)
            M2[b] = fmaxf(M2[b], __shfl_xor_sync(0xffffffffu, M2[b], off));
    if (lane == 0)
#pragma unroll
        for (int b = 0; b < BB; b++) wred[wid][b] = M2[b];
    __syncthreads();
    if (tid < BB) {
        float m2 = wred[0][tid];
#pragma unroll
        for (int w = 1; w < 8; w++) m2 = fmaxf(m2, wred[w][tid]);
        float z = g_f1[tid * NN + i] + m2;
        g_m[tid * NN + i] = fmaxf(z, ALPHA * z);
    }
}

// ---------------------------------------------------------------------------
// Kernel 3: PV via bf16 mma.sync (3-product split). cp.async double-buffered
// H tiles; adj as prefetched bitmask registers; log2-domain softmax scores.
// ---------------------------------------------------------------------------
static constexpr int BPITCH = 144;                // 72 bf16 row pitch (pad)
static constexpr int BPLANE = 64 * BPITCH;        // 9216 B per plane
static constexpr int BBUF   = 2 * BPLANE;         // hi+lo per buffer

__global__ __launch_bounds__(256) void k_pv(float* __restrict__ out)
{
    __shared__ __align__(16) char bsm[2 * BBUF];  // double-buffered tiles
    __shared__ float f2s[2][64];

    const int tid = threadIdx.x, wid = tid >> 5, lane = tid & 31;
    const int g = lane >> 2, tg = lane & 3;
    const int b = blockIdx.y, i0 = blockIdx.x * 128;
    const int gi0 = i0 + wid * 16 + g, gi1 = gi0 + 8;

    const float f1L0 = g_f1[b * NN + gi0] * L2E;
    const float mL0  = g_m [b * NN + gi0] * L2E;
    const float f1L1 = g_f1[b * NN + gi1] * L2E;
    const float mL1  = g_m [b * NN + gi1] * L2E;
    const uint2* bp0 = (const uint2*)(g_adjbits + (size_t)gi0 * 128);
    const uint2* bp1 = (const uint2*)(g_adjbits + (size_t)gi1 * 128);

    const uint32_t sbase  = smem_u32(bsm);
    const uint32_t f2base = smem_u32(f2s);

    auto stage = [&](int c, int buf) {
        const int jc = c * 64;
#pragma unroll
        for (int t = 0; t < 4; t++) {
            int idx = tid + t * 256;               // 0..1023
            int plane = idx >> 9, rr = (idx >> 3) & 63, q = idx & 7;
            const __nv_bfloat16* src =
                (plane ? g_hTlo : g_hThi) + (size_t)(b * CC + rr) * NN + jc + q * 8;
            uint32_t dst = sbase + buf * BBUF + plane * BPLANE + rr * BPITCH + q * 16;
            asm volatile("cp.async.cg.shared.global [%0], [%1], 16;"
                         :: "r"(dst), "l"(src));
        }
        if (tid < 64) {
            const float* src = g_f2t + (jc + tid) * 4 + b;
            uint32_t dst = f2base + (buf * 64 + tid) * 4;
            asm volatile("cp.async.ca.shared.global [%0], [%1], 4;"
                         :: "r"(dst), "l"(src));
        }
    };

    float C[8][4];
#pragma unroll
    for (int n = 0; n < 8; n++)
#pragma unroll
        for (int k = 0; k < 4; k++) C[n][k] = 0.f;
    float rs0 = 0.f, rs1 = 0.f;

    stage(0, 0);
    asm volatile("cp.async.commit_group;" ::: "memory");
    uint2 bits0 = bp0[0], bits1 = bp1[0];

    for (int c = 0; c < 64; ++c) {
        const int buf = c & 1;
        if (c < 63) stage(c + 1, buf ^ 1);
        asm volatile("cp.async.commit_group;" ::: "memory");
        uint2 nb0 = bits0, nb1 = bits1;
        if (c < 63) { nb0 = bp0[c + 1]; nb1 = bp1[c + 1]; }
        asm volatile("cp.async.wait_group 1;" ::: "memory");
        __syncthreads();

        const char*  bb_ = bsm + buf * BBUF;
        const float* f2p = f2s[buf];

#pragma unroll
        for (int ks = 0; ks < 4; ++ks) {
            const uint32_t w0 = (ks < 2) ? bits0.x : bits0.y;
            const uint32_t w1 = (ks < 2) ? bits1.x : bits1.y;
            const int sh = 2 * tg + 16 * (ks & 1);
            const uint32_t s0 = w0 >> sh;
            const uint32_t s1 = w1 >> sh;
            const int c0 = 2 * tg + 16 * ks;
            const float f2a = f2p[c0],     f2b = f2p[c0 + 1];
            const float f2c = f2p[c0 + 8], f2d = f2p[c0 + 9];

            float z, l, e;
#define PVAL(F1L, ML, F2) \
    (z = fmaf((F2), L2E, (F1L)), l = fmaxf(z, ALPHA * z) - (ML), \
     ({ asm("ex2.approx.f32 %0, %1;" : "=f"(e) : "f"(l)); e; }))
            float p00 = (s0 & 1u)     ? PVAL(f1L0, mL0, f2a) : 0.f;
            float p01 = (s0 & 2u)     ? PVAL(f1L0, mL0, f2b) : 0.f;
            float p02 = (s0 & 0x100u) ? PVAL(f1L0, mL0, f2c) : 0.f;
            float p03 = (s0 & 0x200u) ? PVAL(f1L0, mL0, f2d) : 0.f;
            float p10 = (s1 & 1u)     ? PVAL(f1L1, mL1, f2a) : 0.f;
            float p11 = (s1 & 2u)     ? PVAL(f1L1, mL1, f2b) : 0.f;
            float p12 = (s1 & 0x100u) ? PVAL(f1L1, mL1, f2c) : 0.f;
            float p13 = (s1 & 0x200u) ? PVAL(f1L1, mL1, f2d) : 0.f;
#undef PVAL

            rs0 += (p00 + p01) + (p02 + p03);
            rs1 += (p10 + p11) + (p12 + p13);

            // truncation split: hi = bf16 truncation (LOP3), lo = exact remainder
            uint32_t u00 = __float_as_uint(p00) & 0xFFFF0000u;
            uint32_t u01 = __float_as_uint(p01) & 0xFFFF0000u;
            uint32_t u02 = __float_as_uint(p02) & 0xFFFF0000u;
            uint32_t u03 = __float_as_uint(p03) & 0xFFFF0000u;
            uint32_t u10 = __float_as_uint(p10) & 0xFFFF0000u;
            uint32_t u11 = __float_as_uint(p11) & 0xFFFF0000u;
            uint32_t u12 = __float_as_uint(p12) & 0xFFFF0000u;
            uint32_t u13 = __float_as_uint(p13) & 0xFFFF0000u;
            uint32_t ahi0 = __byte_perm(u00, u01, 0x7632);
            uint32_t ahi1 = __byte_perm(u10, u11, 0x7632);
            uint32_t ahi2 = __byte_perm(u02, u03, 0x7632);
            uint32_t ahi3 = __byte_perm(u12, u13, 0x7632);
            uint32_t alo0 = pack_bf2(p00 - __uint_as_float(u00),
                                     p01 - __uint_as_float(u01));
            uint32_t alo1 = pack_bf2(p10 - __uint_as_float(u10),
                                     p11 - __uint_as_float(u11));
            uint32_t alo2 = pack_bf2(p02 - __uint_as_float(u02),
                                     p03 - __uint_as_float(u03));
            uint32_t alo3 = pack_bf2(p12 - __uint_as_float(u12),
                                     p13 - __uint_as_float(u13));

#pragma unroll
            for (int n0 = 0; n0 < 8; ++n0) {
                const uint32_t* rhi =
                    (const uint32_t*)(bb_ + (n0 * 8 + g) * BPITCH);
                const uint32_t* rlo =
                    (const uint32_t*)(bb_ + BPLANE + (n0 * 8 + g) * BPITCH);
                uint32_t bhi0 = rhi[tg + 8 * ks];
                uint32_t bhi1 = rhi[tg + 8 * ks + 4];
                uint32_t blo0 = rlo[tg + 8 * ks];
                uint32_t blo1 = rlo[tg + 8 * ks + 4];
                mma_bf16(C[n0], ahi0, ahi1, ahi2, ahi3, bhi0, bhi1);
                mma_bf16(C[n0], ahi0, ahi1, ahi2, ahi3, blo0, blo1);
                mma_bf16(C[n0], alo0, alo1, alo2, alo3, bhi0, bhi1);
            }
        }
        __syncthreads();
        bits0 = nb0; bits1 = nb1;
    }

    // ---- softmax denominators: quad reduce (lanes sharing a row) ----
    rs0 += __shfl_xor_sync(0xffffffffu, rs0, 1);
    rs0 += __shfl_xor_sync(0xffffffffu, rs0, 2);
    rs1 += __shfl_xor_sync(0xffffffffu, rs1, 1);
    rs1 += __shfl_xor_sync(0xffffffffu, rs1, 2);
    float iv0 = 1.0f / rs0, iv1 = 1.0f / rs1;

    // ---- epilogue: scale, relu, store float2 per slot ----
    float* o0 = out + ((size_t)b * NN + gi0) * CC + 2 * tg;
    float* o1 = out + ((size_t)b * NN + gi1) * CC + 2 * tg;
#pragma unroll
    for (int n0 = 0; n0 < 8; ++n0) {
        float2 v0, v1;
        v0.x = fmaxf(C[n0][0] * iv0, 0.f);
        v0.y = fmaxf(C[n0][1] * iv0, 0.f);
        v1.x = fmaxf(C[n0][2] * iv1, 0.f);
        v1.y = fmaxf(C[n0][3] * iv1, 0.f);
        *(float2*)(o0 + n0 * 8) = v0;
        *(float2*)(o1 + n0 * 8) = v1;
    }
}

// ---------------------------------------------------------------------------
extern "C" void kernel_launch(void* const* d_in, const int* in_sizes, int n_in,
                              void* d_out, int out_size)
{
    const float* x   = (const float*)d_in[0];   // [4,4096,64] f32
    const int*   adj = (const int*)  d_in[1];   // [4096,4096] i32
    const float* W   = (const float*)d_in[2];   // [64,64] f32
    const float* a   = (const float*)d_in[3];   // [128,1] f32
    float*       out = (float*)d_out;           // [4,4096,64] f32

    k_proj<<<BB * NN / 16, 256>>>(x, W, a);
    k_rowmax<<<NN, 256>>>(adj);
    dim3 grid(NN / 128, BB);
    k_pv<<<grid, 256>>>(out);
}

// round 6
// speedup vs baseline: 2.6144x; 1.2336x over previous
#include <cuda_runtime.h>
#include <cuda_fp16.h>
#include <cstdint>
#include <cstddef>

#define ALPHA 0.2f
#define L2E   1.4426950408889634f

static constexpr int BB = 4;
static constexpr int NN = 4096;
static constexpr int CC = 64;

// ---------------------------------------------------------------------------
// Scratch (__device__ globals: allocation-free rule)
// ---------------------------------------------------------------------------
__device__ __half    g_hT [BB * CC * NN];        // [b][f][n]  fp16 h^T
__device__ float     g_f1 [BB * NN];             // f1[b][n]
__device__ float     g_f2t[NN * BB];             // f2 transposed: [n][b]
__device__ float     g_m  [BB * NN];             // MASKED row max of e (post-leaky)
__device__ uint32_t  g_adjbits[NN * 128];        // adj rows bit-packed

__device__ __forceinline__ uint32_t smem_u32(const void* p) {
    uint32_t a;
    asm("{ .reg .u64 t; cvta.to.shared.u64 t, %1; cvt.u32.u64 %0, t; }"
        : "=r"(a) : "l"(p));
    return a;
}

// pack two f32 -> f16x2 (first arg in LOW half)
__device__ __forceinline__ uint32_t pack_h2(float lo, float hi) {
    uint32_t d;
    asm("cvt.rn.f16x2.f32 %0, %1, %2;" : "=r"(d) : "f"(hi), "f"(lo));
    return d;
}

__device__ __forceinline__ void mma_f16(float c[4], uint32_t a0, uint32_t a1,
                                        uint32_t a2, uint32_t a3,
                                        uint32_t b0, uint32_t b1) {
    asm volatile(
        "mma.sync.aligned.m16n8k16.row.col.f32.f16.f16.f32 "
        "{%0,%1,%2,%3}, {%4,%5,%6,%7}, {%8,%9}, {%0,%1,%2,%3};"
        : "+f"(c[0]), "+f"(c[1]), "+f"(c[2]), "+f"(c[3])
        : "r"(a0), "r"(a1), "r"(a2), "r"(a3), "r"(b0), "r"(b1));
}

// ---------------------------------------------------------------------------
// Kernel 1: h = x@W ; f1 = h.a1 ; f2 = h.a2 ; h^T stored fp16 [b][f][n].
// ---------------------------------------------------------------------------
__global__ __launch_bounds__(256) void k_proj(const float* __restrict__ x,
                                              const float* __restrict__ W,
                                              const float* __restrict__ a)
{
    __shared__ float Ws[64][64];
    __shared__ float xs[16][64];
    __shared__ float hsm[64][17];
    __shared__ float red1[8][4], red2[8][4];

    int tid  = threadIdx.x;
    int row0 = blockIdx.x * 16;
    int bb   = row0 >> 12;
    int n0   = row0 & (NN - 1);

#pragma unroll
    for (int t = 0; t < 16; t++) {
        int idx = tid + t * 256;
        Ws[idx >> 6][idx & 63] = W[idx];
    }
#pragma unroll
    for (int t = 0; t < 4; t++) {
        int idx = tid + t * 256;
        xs[idx >> 6][idx & 63] = x[(size_t)row0 * CC + idx];
    }
    __syncthreads();

    int slot = tid >> 6, f = tid & 63, w = tid >> 5;
    float a1v = a[f], a2v = a[64 + f];

#pragma unroll
    for (int rr = 0; rr < 4; ++rr) {
        int r = slot * 4 + rr;
        float hv = 0.f;
#pragma unroll
        for (int k = 0; k < 64; k++) hv = fmaf(xs[r][k], Ws[k][f], hv);
        hsm[f][r] = hv;

        float v1 = hv * a1v, v2 = hv * a2v;
#pragma unroll
        for (int off = 16; off; off >>= 1) {
            v1 += __shfl_down_sync(0xffffffffu, v1, off);
            v2 += __shfl_down_sync(0xffffffffu, v2, off);
        }
        if ((tid & 31) == 0) { red1[w][rr] = v1; red2[w][rr] = v2; }
    }
    __syncthreads();

    // transposed fp16 write: 512 pairs, 2 per thread
#pragma unroll
    for (int t = 0; t < 2; t++) {
        int idx = tid + t * 256;            // 0..511
        int ff = idx >> 3, p = idx & 7;
        float v0 = hsm[ff][2 * p], v1 = hsm[ff][2 * p + 1];
        size_t base = ((size_t)(bb * CC + ff)) * NN + n0 + 2 * p;
        *(uint32_t*)(g_hT + base) = pack_h2(v0, v1);
    }

    if (tid < 16) {
        int s = tid & 3, rr = tid >> 2;
        int g = row0 + s * 4 + rr;
        g_f1[g] = red1[2 * s][rr] + red1[2 * s + 1][rr];
        float v2 = red2[2 * s][rr] + red2[2 * s + 1][rr];
        g_f2t[(g & (NN - 1)) * 4 + (g >> 12)] = v2;
    }
}

// ---------------------------------------------------------------------------
// Kernel 2: MASKED row max (leaky monotone -> no exp) + adj bit-packing.
// Single adjacency pass; row cached in SMEM.
// ---------------------------------------------------------------------------
__global__ __launch_bounds__(256) void k_rowmax(const int* __restrict__ adj)
{
    __shared__ int   arow[NN];
    __shared__ float wred[8][BB];

    int i = blockIdx.x, tid = threadIdx.x;
    int wid = tid >> 5, lane = tid & 31;
    const int4* src = (const int4*)(adj + ((size_t)i << 12));
    int4* dst = (int4*)arow;
#pragma unroll
    for (int t = 0; t < 4; t++) dst[tid + t * 256] = src[tid + t * 256];
    __syncthreads();

    // pack adjacency bits: warp wid covers j in [wid*512, wid*512+512)
#pragma unroll
    for (int t = 0; t < 16; t++) {
        int j = wid * 512 + t * 32 + lane;
        unsigned bal = __ballot_sync(0xffffffffu, arow[j] > 0);
        if (lane == 0) g_adjbits[(size_t)i * 128 + wid * 16 + t] = bal;
    }

    float M2[BB];
#pragma unroll
    for (int b = 0; b < BB; b++) M2[b] = -3.0e38f;

#pragma unroll 4
    for (int t = 0; t < 16; t++) {
        int j  = tid + t * 256;
        int av = arow[j];
        float4 f2 = *(const float4*)(g_f2t + j * 4);
        M2[0] = fmaxf(M2[0], (av > 0) ? f2.x : -3.0e38f);
        M2[1] = fmaxf(M2[1], (av > 0) ? f2.y : -3.0e38f);
        M2[2] = fmaxf(M2[2], (av > 0) ? f2.z : -3.0e38f);
        M2[3] = fmaxf(M2[3], (av > 0) ? f2.w : -3.0e38f);
    }
#pragma unroll
    for (int off = 16; off; off >>= 1)
#pragma unroll
        for (int b = 0; b < BB; b++)
            M2[b] = fmaxf(M2[b], __shfl_xor_sync(0xffffffffu, M2[b], off));
    if (lane == 0)
#pragma unroll
        for (int b = 0; b < BB; b++) wred[wid][b] = M2[b];
    __syncthreads();
    if (tid < BB) {
        float m2 = wred[0][tid];
#pragma unroll
        for (int w = 1; w < 8; w++) m2 = fmaxf(m2, wred[w][tid]);
        float z = g_f1[tid * NN + i] + m2;
        g_m[tid * NN + i] = fmaxf(z, ALPHA * z);   // masked leaky max
    }
}

// ---------------------------------------------------------------------------
// Kernel 3: PV via fp16 mma.sync (single product). cp.async double-buffered
// H tiles; adj bitmask prefetch; log2-domain scores.
// ---------------------------------------------------------------------------
static constexpr int BPITCH = 144;               // 72 fp16 row pitch (pad)
static constexpr int BPLANE = 64 * BPITCH;       // 9216 B per buffer

__global__ __launch_bounds__(256) void k_pv(float* __restrict__ out)
{
    __shared__ __align__(16) char bsm[2 * BPLANE];
    __shared__ float f2s[2][64];

    const int tid = threadIdx.x, wid = tid >> 5, lane = tid & 31;
    const int g = lane >> 2, tg = lane & 3;
    const int b = blockIdx.y, i0 = blockIdx.x * 128;
    const int gi0 = i0 + wid * 16 + g, gi1 = gi0 + 8;

    const float f1L0 = g_f1[b * NN + gi0] * L2E;
    const float mL0  = g_m [b * NN + gi0] * L2E;
    const float f1L1 = g_f1[b * NN + gi1] * L2E;
    const float mL1  = g_m [b * NN + gi1] * L2E;

    const uint2* bp0 = (const uint2*)(g_adjbits + (size_t)gi0 * 128);
    const uint2* bp1 = (const uint2*)(g_adjbits + (size_t)gi1 * 128);

    const uint32_t sbase  = smem_u32(bsm);
    const uint32_t f2base = smem_u32(f2s);

    auto stage = [&](int c, int buf) {
        const int jc = c * 64;
#pragma unroll
        for (int t = 0; t < 2; t++) {
            int k = (tid << 1) + t;              // 0..511 chunks of 16B
            int rr = k >> 3, q = k & 7;
            const __half* src = g_hT + (size_t)(b * CC + rr) * NN + jc + q * 8;
            uint32_t dst = sbase + buf * BPLANE + rr * BPITCH + q * 16;
            asm volatile("cp.async.cg.shared.global [%0], [%1], 16;"
                         :: "r"(dst), "l"(src));
        }
        if (tid < 64) {
            const float* src = g_f2t + (jc + tid) * 4 + b;
            uint32_t dst = f2base + (buf * 64 + tid) * 4;
            asm volatile("cp.async.ca.shared.global [%0], [%1], 4;"
                         :: "r"(dst), "l"(src));
        }
    };

    float C[8][4];
#pragma unroll
    for (int n = 0; n < 8; n++)
#pragma unroll
        for (int k = 0; k < 4; k++) C[n][k] = 0.f;
    float rs0 = 0.f, rs1 = 0.f;

    stage(0, 0);
    asm volatile("cp.async.commit_group;" ::: "memory");
    uint2 bits0 = bp0[0], bits1 = bp1[0];

    for (int c = 0; c < 64; ++c) {
        const int buf = c & 1;
        if (c < 63) stage(c + 1, buf ^ 1);
        asm volatile("cp.async.commit_group;" ::: "memory");
        uint2 nb0 = bits0, nb1 = bits1;
        if (c < 63) { nb0 = bp0[c + 1]; nb1 = bp1[c + 1]; }
        asm volatile("cp.async.wait_group 1;" ::: "memory");
        __syncthreads();

        const char*  bb_ = bsm + buf * BPLANE;
        const float* f2p = f2s[buf];

#pragma unroll
        for (int ks = 0; ks < 4; ++ks) {
            const uint32_t w0 = (ks < 2) ? bits0.x : bits0.y;
            const uint32_t w1 = (ks < 2) ? bits1.x : bits1.y;
            const int sh = 2 * tg + 16 * (ks & 1);
            const uint32_t s0 = w0 >> sh;
            const uint32_t s1 = w1 >> sh;
            const int c0 = 2 * tg + 16 * ks;
            const float f2a = f2p[c0],     f2b = f2p[c0 + 1];
            const float f2c = f2p[c0 + 8], f2d = f2p[c0 + 9];

            float z, l, e;
#define PVAL(F1L, ML, F2) \
    (z = fmaf((F2), L2E, (F1L)), l = fmaxf(z, ALPHA * z) - (ML), \
     ({ asm("ex2.approx.f32 %0, %1;" : "=f"(e) : "f"(l)); e; }))
            float p00 = (s0 & 1u)     ? PVAL(f1L0, mL0, f2a) : 0.f;
            float p01 = (s0 & 2u)     ? PVAL(f1L0, mL0, f2b) : 0.f;
            float p02 = (s0 & 0x100u) ? PVAL(f1L0, mL0, f2c) : 0.f;
            float p03 = (s0 & 0x200u) ? PVAL(f1L0, mL0, f2d) : 0.f;
            float p10 = (s1 & 1u)     ? PVAL(f1L1, mL1, f2a) : 0.f;
            float p11 = (s1 & 2u)     ? PVAL(f1L1, mL1, f2b) : 0.f;
            float p12 = (s1 & 0x100u) ? PVAL(f1L1, mL1, f2c) : 0.f;
            float p13 = (s1 & 0x200u) ? PVAL(f1L1, mL1, f2d) : 0.f;
#undef PVAL

            rs0 += (p00 + p01) + (p02 + p03);
            rs1 += (p10 + p11) + (p12 + p13);

            uint32_t a0 = pack_h2(p00, p01);
            uint32_t a1 = pack_h2(p10, p11);
            uint32_t a2 = pack_h2(p02, p03);
            uint32_t a3 = pack_h2(p12, p13);

#pragma unroll
            for (int n0 = 0; n0 < 8; ++n0) {
                const uint32_t* rh =
                    (const uint32_t*)(bb_ + (n0 * 8 + g) * BPITCH);
                uint32_t b0 = rh[tg + 8 * ks];
                uint32_t b1 = rh[tg + 8 * ks + 4];
                mma_f16(C[n0], a0, a1, a2, a3, b0, b1);
            }
        }
        __syncthreads();
        bits0 = nb0; bits1 = nb1;
    }

    // ---- softmax denominators: quad reduce (lanes sharing a row) ----
    rs0 += __shfl_xor_sync(0xffffffffu, rs0, 1);
    rs0 += __shfl_xor_sync(0xffffffffu, rs0, 2);
    rs1 += __shfl_xor_sync(0xffffffffu, rs1, 1);
    rs1 += __shfl_xor_sync(0xffffffffu, rs1, 2);
    float iv0 = 1.0f / rs0, iv1 = 1.0f / rs1;

    // ---- epilogue: scale, relu, store float2 per slot ----
    float* o0 = out + ((size_t)b * NN + gi0) * CC + 2 * tg;
    float* o1 = out + ((size_t)b * NN + gi1) * CC + 2 * tg;
#pragma unroll
    for (int n0 = 0; n0 < 8; ++n0) {
        float2 v0, v1;
        v0.x = fmaxf(C[n0][0] * iv0, 0.f);
        v0.y = fmaxf(C[n0][1] * iv0, 0.f);
        v1.x = fmaxf(C[n0][2] * iv1, 0.f);
        v1.y = fmaxf(C[n0][3] * iv1, 0.f);
        *(float2*)(o0 + n0 * 8) = v0;
        *(float2*)(o1 + n0 * 8) = v1;
    }
}

// ---------------------------------------------------------------------------
extern "C" void kernel_launch(void* const* d_in, const int* in_sizes, int n_in,
                              void* d_out, int out_size)
{
    const float* x   = (const float*)d_in[0];   // [4,4096,64] f32
    const int*   adj = (const int*)  d_in[1];   // [4096,4096] i32
    const float* W   = (const float*)d_in[2];   // [64,64] f32
    const float* a   = (const float*)d_in[3];   // [128,1] f32
    float*       out = (float*)d_out;           // [4,4096,64] f32

    k_proj<<<BB * NN / 16, 256>>>(x, W, a);
    k_rowmax<<<NN, 256>>>(adj);
    dim3 grid(NN / 128, BB);
    k_pv<<<grid, 256>>>(out);
}

// round 7
// speedup vs baseline: 3.5009x; 1.3391x over previous
#include <cuda_runtime.h>
#include <cuda_fp16.h>
#include <cstdint>
#include <cstddef>

#define ALPHA 0.2f
#define L2E   1.4426950408889634f

static constexpr int BB = 4;
static constexpr int NN = 4096;
static constexpr int CC = 64;

// ---------------------------------------------------------------------------
// Scratch (__device__ globals: allocation-free rule)
// ---------------------------------------------------------------------------
__device__ __half    g_hT [BB * CC * NN];        // [b][f][n]  fp16 h^T
__device__ float     g_f1 [BB * NN];             // f1[b][n]
__device__ float     g_f2t[NN * BB];             // f2 transposed: [n][b]
__device__ float     g_m  [BB * NN];             // MASKED row max of e (post-leaky)
__device__ uint32_t  g_adjbits[NN * 128];        // adj rows bit-packed
__device__ float     g_pC [2 * BB * NN * CC];    // partial PV per j-half
__device__ float     g_prs[2 * BB * NN];         // partial row sums per j-half

__device__ __forceinline__ uint32_t smem_u32(const void* p) {
    uint32_t a;
    asm("{ .reg .u64 t; cvta.to.shared.u64 t, %1; cvt.u32.u64 %0, t; }"
        : "=r"(a) : "l"(p));
    return a;
}

// pack two f32 -> f16x2 (first arg in LOW half)
__device__ __forceinline__ uint32_t pack_h2(float lo, float hi) {
    uint32_t d;
    asm("cvt.rn.f16x2.f32 %0, %1, %2;" : "=r"(d) : "f"(hi), "f"(lo));
    return d;
}

__device__ __forceinline__ void mma_f16(float c[4], uint32_t a0, uint32_t a1,
                                        uint32_t a2, uint32_t a3,
                                        uint32_t b0, uint32_t b1) {
    asm volatile(
        "mma.sync.aligned.m16n8k16.row.col.f32.f16.f16.f32 "
        "{%0,%1,%2,%3}, {%4,%5,%6,%7}, {%8,%9}, {%0,%1,%2,%3};"
        : "+f"(c[0]), "+f"(c[1]), "+f"(c[2]), "+f"(c[3])
        : "r"(a0), "r"(a1), "r"(a2), "r"(a3), "r"(b0), "r"(b1));
}

// ---------------------------------------------------------------------------
// Kernel 1: h = x@W ; f1 = h.a1 ; f2 = h.a2 ; h^T stored fp16 [b][f][n].
// ---------------------------------------------------------------------------
__global__ __launch_bounds__(256) void k_proj(const float* __restrict__ x,
                                              const float* __restrict__ W,
                                              const float* __restrict__ a)
{
    __shared__ float Ws[64][64];
    __shared__ float xs[16][64];
    __shared__ float hsm[64][17];
    __shared__ float red1[8][4], red2[8][4];

    int tid  = threadIdx.x;
    int row0 = blockIdx.x * 16;
    int bb   = row0 >> 12;
    int n0   = row0 & (NN - 1);

#pragma unroll
    for (int t = 0; t < 16; t++) {
        int idx = tid + t * 256;
        Ws[idx >> 6][idx & 63] = W[idx];
    }
#pragma unroll
    for (int t = 0; t < 4; t++) {
        int idx = tid + t * 256;
        xs[idx >> 6][idx & 63] = x[(size_t)row0 * CC + idx];
    }
    __syncthreads();

    int slot = tid >> 6, f = tid & 63, w = tid >> 5;
    float a1v = a[f], a2v = a[64 + f];

#pragma unroll
    for (int rr = 0; rr < 4; ++rr) {
        int r = slot * 4 + rr;
        float hv = 0.f;
#pragma unroll
        for (int k = 0; k < 64; k++) hv = fmaf(xs[r][k], Ws[k][f], hv);
        hsm[f][r] = hv;

        float v1 = hv * a1v, v2 = hv * a2v;
#pragma unroll
        for (int off = 16; off; off >>= 1) {
            v1 += __shfl_down_sync(0xffffffffu, v1, off);
            v2 += __shfl_down_sync(0xffffffffu, v2, off);
        }
        if ((tid & 31) == 0) { red1[w][rr] = v1; red2[w][rr] = v2; }
    }
    __syncthreads();

#pragma unroll
    for (int t = 0; t < 2; t++) {
        int idx = tid + t * 256;            // 0..511
        int ff = idx >> 3, p = idx & 7;
        float v0 = hsm[ff][2 * p], v1 = hsm[ff][2 * p + 1];
        size_t base = ((size_t)(bb * CC + ff)) * NN + n0 + 2 * p;
        *(uint32_t*)(g_hT + base) = pack_h2(v0, v1);
    }

    if (tid < 16) {
        int s = tid & 3, rr = tid >> 2;
        int g = row0 + s * 4 + rr;
        g_f1[g] = red1[2 * s][rr] + red1[2 * s + 1][rr];
        float v2 = red2[2 * s][rr] + red2[2 * s + 1][rr];
        g_f2t[(g & (NN - 1)) * 4 + (g >> 12)] = v2;
    }
}

// ---------------------------------------------------------------------------
// Kernel 2: MASKED row max (leaky monotone -> no exp) + adj bit-packing.
// ---------------------------------------------------------------------------
__global__ __launch_bounds__(256) void k_rowmax(const int* __restrict__ adj)
{
    __shared__ int   arow[NN];
    __shared__ float wred[8][BB];

    int i = blockIdx.x, tid = threadIdx.x;
    int wid = tid >> 5, lane = tid & 31;
    const int4* src = (const int4*)(adj + ((size_t)i << 12));
    int4* dst = (int4*)arow;
#pragma unroll
    for (int t = 0; t < 4; t++) dst[tid + t * 256] = src[tid + t * 256];
    __syncthreads();

#pragma unroll
    for (int t = 0; t < 16; t++) {
        int j = wid * 512 + t * 32 + lane;
        unsigned bal = __ballot_sync(0xffffffffu, arow[j] > 0);
        if (lane == 0) g_adjbits[(size_t)i * 128 + wid * 16 + t] = bal;
    }

    float M2[BB];
#pragma unroll
    for (int b = 0; b < BB; b++) M2[b] = -3.0e38f;

#pragma unroll 4
    for (int t = 0; t < 16; t++) {
        int j  = tid + t * 256;
        int av = arow[j];
        float4 f2 = *(const float4*)(g_f2t + j * 4);
        M2[0] = fmaxf(M2[0], (av > 0) ? f2.x : -3.0e38f);
        M2[1] = fmaxf(M2[1], (av > 0) ? f2.y : -3.0e38f);
        M2[2] = fmaxf(M2[2], (av > 0) ? f2.z : -3.0e38f);
        M2[3] = fmaxf(M2[3], (av > 0) ? f2.w : -3.0e38f);
    }
#pragma unroll
    for (int off = 16; off; off >>= 1)
#pragma unroll
        for (int b = 0; b < BB; b++)
            M2[b] = fmaxf(M2[b], __shfl_xor_sync(0xffffffffu, M2[b], off));
    if (lane == 0)
#pragma unroll
        for (int b = 0; b < BB; b++) wred[wid][b] = M2[b];
    __syncthreads();
    if (tid < BB) {
        float m2 = wred[0][tid];
#pragma unroll
        for (int w = 1; w < 8; w++) m2 = fmaxf(m2, wred[w][tid]);
        float z = g_f1[tid * NN + i] + m2;
        g_m[tid * NN + i] = fmaxf(z, ALPHA * z);
    }
}

// ---------------------------------------------------------------------------
// Kernel 3: partial PV via fp16 mma.sync. 64 i-rows x 2048 j per CTA
// (j split over gridDim.z). 128 threads (4 warps x 16 rows). TJ=128 chunks.
// ---------------------------------------------------------------------------
static constexpr int TJ     = 128;
static constexpr int NCH    = 2048 / TJ;          // 16 chunks per CTA
static constexpr int BPITCH = 272;                // 128 fp16 + 16B pad
static constexpr int BPLANE = 64 * BPITCH;        // 17408 B per buffer

__global__ __launch_bounds__(128) void k_pv()
{
    __shared__ __align__(16) char bsm[2 * BPLANE];
    __shared__ float f2s[2][TJ];

    const int tid = threadIdx.x, wid = tid >> 5, lane = tid & 31;
    const int g = lane >> 2, tg = lane & 3;
    const int b = blockIdx.y, i0 = blockIdx.x * 64;
    const int half = blockIdx.z;
    const int jbase = half * 2048;
    const int gi0 = i0 + wid * 16 + g, gi1 = gi0 + 8;

    const float f1L0 = g_f1[b * NN + gi0] * L2E;
    const float mL0  = g_m [b * NN + gi0] * L2E;
    const float f1L1 = g_f1[b * NN + gi1] * L2E;
    const float mL1  = g_m [b * NN + gi1] * L2E;

    const uint4* bp0 = (const uint4*)(g_adjbits + (size_t)gi0 * 128 + half * 64);
    const uint4* bp1 = (const uint4*)(g_adjbits + (size_t)gi1 * 128 + half * 64);

    const uint32_t sbase  = smem_u32(bsm);
    const uint32_t f2base = smem_u32(f2s);

    auto stage = [&](int c, int buf) {
        const int jc = jbase + c * TJ;
#pragma unroll
        for (int t = 0; t < 8; t++) {
            int k = (tid << 3) + t;              // 0..1023 chunks of 16B
            int rr = k >> 4, q = k & 15;
            const __half* src = g_hT + (size_t)(b * CC + rr) * NN + jc + q * 8;
            uint32_t dst = sbase + buf * BPLANE + rr * BPITCH + q * 16;
            asm volatile("cp.async.cg.shared.global [%0], [%1], 16;"
                         :: "r"(dst), "l"(src));
        }
        {
            const float* src = g_f2t + (jc + tid) * 4 + b;
            uint32_t dst = f2base + (buf * TJ + tid) * 4;
            asm volatile("cp.async.ca.shared.global [%0], [%1], 4;"
                         :: "r"(dst), "l"(src));
        }
    };

    float C[8][4];
#pragma unroll
    for (int n = 0; n < 8; n++)
#pragma unroll
        for (int k = 0; k < 4; k++) C[n][k] = 0.f;
    float rs0 = 0.f, rs1 = 0.f;

    stage(0, 0);
    asm volatile("cp.async.commit_group;" ::: "memory");
    uint4 bits0 = bp0[0], bits1 = bp1[0];

    for (int c = 0; c < NCH; ++c) {
        const int buf = c & 1;
        if (c < NCH - 1) stage(c + 1, buf ^ 1);
        asm volatile("cp.async.commit_group;" ::: "memory");
        uint4 nb0 = bits0, nb1 = bits1;
        if (c < NCH - 1) { nb0 = bp0[c + 1]; nb1 = bp1[c + 1]; }
        asm volatile("cp.async.wait_group 1;" ::: "memory");
        __syncthreads();

        const char*  bb_ = bsm + buf * BPLANE;
        const float* f2p = f2s[buf];

#pragma unroll
        for (int ks = 0; ks < 8; ++ks) {
            const uint32_t w0 = (ks < 2) ? bits0.x : (ks < 4) ? bits0.y
                              : (ks < 6) ? bits0.z : bits0.w;
            const uint32_t w1 = (ks < 2) ? bits1.x : (ks < 4) ? bits1.y
                              : (ks < 6) ? bits1.z : bits1.w;
            const int sh = 2 * tg + 16 * (ks & 1);
            const uint32_t s0 = w0 >> sh;
            const uint32_t s1 = w1 >> sh;
            const int c0 = 2 * tg + 16 * ks;
            const float f2a = f2p[c0],     f2b = f2p[c0 + 1];
            const float f2c = f2p[c0 + 8], f2d = f2p[c0 + 9];

            float z, l, e;
#define PVAL(F1L, ML, F2) \
    (z = fmaf((F2), L2E, (F1L)), l = fmaxf(z, ALPHA * z) - (ML), \
     ({ asm("ex2.approx.f32 %0, %1;" : "=f"(e) : "f"(l)); e; }))
            float p00 = (s0 & 1u)     ? PVAL(f1L0, mL0, f2a) : 0.f;
            float p01 = (s0 & 2u)     ? PVAL(f1L0, mL0, f2b) : 0.f;
            float p02 = (s0 & 0x100u) ? PVAL(f1L0, mL0, f2c) : 0.f;
            float p03 = (s0 & 0x200u) ? PVAL(f1L0, mL0, f2d) : 0.f;
            float p10 = (s1 & 1u)     ? PVAL(f1L1, mL1, f2a) : 0.f;
            float p11 = (s1 & 2u)     ? PVAL(f1L1, mL1, f2b) : 0.f;
            float p12 = (s1 & 0x100u) ? PVAL(f1L1, mL1, f2c) : 0.f;
            float p13 = (s1 & 0x200u) ? PVAL(f1L1, mL1, f2d) : 0.f;
#undef PVAL

            rs0 += (p00 + p01) + (p02 + p03);
            rs1 += (p10 + p11) + (p12 + p13);

            uint32_t a0 = pack_h2(p00, p01);
            uint32_t a1 = pack_h2(p10, p11);
            uint32_t a2 = pack_h2(p02, p03);
            uint32_t a3 = pack_h2(p12, p13);

#pragma unroll
            for (int n0 = 0; n0 < 8; ++n0) {
                const uint32_t* rh =
                    (const uint32_t*)(bb_ + (n0 * 8 + g) * BPITCH);
                uint32_t b0 = rh[tg + 8 * ks];
                uint32_t b1 = rh[tg + 8 * ks + 4];
                mma_f16(C[n0], a0, a1, a2, a3, b0, b1);
            }
        }
        __syncthreads();
        bits0 = nb0; bits1 = nb1;
    }

    // ---- partial row sums: quad reduce over tg lanes ----
    rs0 += __shfl_xor_sync(0xffffffffu, rs0, 1);
    rs0 += __shfl_xor_sync(0xffffffffu, rs0, 2);
    rs1 += __shfl_xor_sync(0xffffffffu, rs1, 1);
    rs1 += __shfl_xor_sync(0xffffffffu, rs1, 2);
    if (tg == 0) {
        g_prs[(size_t)(half * BB + b) * NN + gi0] = rs0;
        g_prs[(size_t)(half * BB + b) * NN + gi1] = rs1;
    }

    // ---- store unnormalized partial C ----
    float* o0 = g_pC + ((size_t)(half * BB + b) * NN + gi0) * CC + 2 * tg;
    float* o1 = g_pC + ((size_t)(half * BB + b) * NN + gi1) * CC + 2 * tg;
#pragma unroll
    for (int n0 = 0; n0 < 8; ++n0) {
        *(float2*)(o0 + n0 * 8) = make_float2(C[n0][0], C[n0][1]);
        *(float2*)(o1 + n0 * 8) = make_float2(C[n0][2], C[n0][3]);
    }
}

// ---------------------------------------------------------------------------
// Kernel 4: combine halves: out = relu((C0+C1) / (rs0+rs1))
// ---------------------------------------------------------------------------
__global__ __launch_bounds__(256) void k_reduce(float* __restrict__ out)
{
    int e = blockIdx.x * 256 + threadIdx.x;   // float4 index, 262144 total
    int row = e >> 4;                          // b*NN + n
    float inv = 1.0f / (g_prs[row] + g_prs[BB * NN + row]);
    const float4* pc = (const float4*)g_pC;
    float4 c0 = pc[e];
    float4 c1 = pc[(BB * NN * CC / 4) + e];
    float4 v;
    v.x = fmaxf((c0.x + c1.x) * inv, 0.f);
    v.y = fmaxf((c0.y + c1.y) * inv, 0.f);
    v.z = fmaxf((c0.z + c1.z) * inv, 0.f);
    v.w = fmaxf((c0.w + c1.w) * inv, 0.f);
    ((float4*)out)[e] = v;
}

// ---------------------------------------------------------------------------
extern "C" void kernel_launch(void* const* d_in, const int* in_sizes, int n_in,
                              void* d_out, int out_size)
{
    const float* x   = (const float*)d_in[0];   // [4,4096,64] f32
    const int*   adj = (const int*)  d_in[1];   // [4096,4096] i32
    const float* W   = (const float*)d_in[2];   // [64,64] f32
    const float* a   = (const float*)d_in[3];   // [128,1] f32
    float*       out = (float*)d_out;           // [4,4096,64] f32

    k_proj<<<BB * NN / 16, 256>>>(x, W, a);
    k_rowmax<<<NN, 256>>>(adj);
    dim3 grid(NN / 64, BB, 2);
    k_pv<<<grid, 128>>>();
    k_reduce<<<BB * NN * CC / 4 / 256, 256>>>(out);
}